// round 12
// baseline (speedup 1.0000x reference)
#include <cuda_runtime.h>
#include <math.h>

// Problem constants
#define BATCH  4
#define SLQ    2048
#define SLK    2048
#define DMODEL 768
#define NHEAD  12
#define DHEAD  64
#define MROWS  (BATCH * SLQ)   // 8192

// ---------------------------------------------------------------------------
// Scratch (device globals; no allocation allowed)
// ---------------------------------------------------------------------------
__device__ float g_q  [(size_t)MROWS * DMODEL];
__device__ float g_k  [(size_t)BATCH * SLK * DMODEL];
__device__ float g_v  [(size_t)BATCH * SLK * DMODEL];
__device__ float g_att[(size_t)MROWS * DMODEL];
__device__ float g_ao [(size_t)MROWS * DMODEL];
__device__ float g_f1 [(size_t)MROWS * DMODEL];
__device__ float g_y  [(size_t)MROWS * DMODEL];
__device__ int   g_valid[BATCH];

// ---------------------------------------------------------------------------
// valid_lens[b] = count of nonzero mask entries in row b
// ---------------------------------------------------------------------------
__global__ void valid_kernel(const int* __restrict__ mask) {
    __shared__ int red[256];
    int b = blockIdx.x;
    int cnt = 0;
    for (int i = threadIdx.x; i < SLK; i += 256)
        cnt += (mask[b * SLK + i] != 0) ? 1 : 0;
    red[threadIdx.x] = cnt;
    __syncthreads();
    for (int s = 128; s > 0; s >>= 1) {
        if (threadIdx.x < s) red[threadIdx.x] += red[threadIdx.x + s];
        __syncthreads();
    }
    if (threadIdx.x == 0) g_valid[b] = red[0];
}

// ---------------------------------------------------------------------------
// TF32 mma helpers
// ---------------------------------------------------------------------------
__device__ __forceinline__ unsigned f2tf(float f) {
    unsigned u;
    asm("cvt.rna.tf32.f32 %0, %1;" : "=r"(u) : "f"(f));
    return u;
}

__device__ __forceinline__ void mma_tf32(float c[4],
                                         const unsigned a[4],
                                         const unsigned b[2]) {
    asm volatile(
        "mma.sync.aligned.m16n8k8.row.col.f32.tf32.tf32.f32 "
        "{%0,%1,%2,%3}, {%4,%5,%6,%7}, {%8,%9}, {%0,%1,%2,%3};"
        : "+f"(c[0]), "+f"(c[1]), "+f"(c[2]), "+f"(c[3])
        : "r"(a[0]), "r"(a[1]), "r"(a[2]), "r"(a[3]),
          "r"(b[0]), "r"(b[1]));
}

// ---------------------------------------------------------------------------
// TF32 tensor-core GEMM core (128x128 tile, BK=16 double-buffered, 8 warps).
// A smem: per-row k-interleaved pairs (k, k+4), stride 24 -> a-frag LDS.64.
// B smem: [kchunk][t][n][pair], t-row stride 264 -> b-frag LDS.64.
// MODE: 0=plain, 1=+bias,ReLU, 2=+bias,+residual(g_ao)
// ---------------------------------------------------------------------------
#define GK DMODEL
#define GN DMODEL
#define ASTR 24
#define BTR  264
#define BCH  (4 * BTR)   // 1056

template<int MODE>
__device__ __forceinline__ void gemm_body(const float* __restrict__ A,
                                          const float* __restrict__ Bm,
                                          float* __restrict__ C,
                                          const float* __restrict__ bias,
                                          unsigned* As,   // [2][128*ASTR]
                                          unsigned* Bs,   // [2][2*BCH]
                                          int bx, int by)
{
    const int tid = threadIdx.x;
    const int warp = tid >> 5;
    const int lane = tid & 31;
    const int wm = warp >> 1;
    const int wn = warp & 1;
    const int g  = lane >> 2;
    const int t  = lane & 3;

    float acc[2][8][4];
#pragma unroll
    for (int mi = 0; mi < 2; mi++)
#pragma unroll
        for (int nj = 0; nj < 8; nj++)
#pragma unroll
            for (int q = 0; q < 4; q++) acc[mi][nj][q] = 0.0f;

    const int arow = tid >> 1;
    const int akc  = (tid & 1) * 8;
    const int bn4  = (tid & 31) * 4;
    const int bkrw = tid >> 5;
    const int bkkc = bkrw >> 2;
    const int btb  = bkrw & 3;

    const float* Ag  = A  + (size_t)(by * 128 + arow) * GK + akc;
    const float* BgL = Bm + (size_t)(bkkc * 8 + btb) * GN + bx * 128 + bn4;

    float4 pa0, pa1, pb0, pb1;

    pa0 = *(const float4*)(Ag);
    pa1 = *(const float4*)(Ag + 4);
    pb0 = *(const float4*)(BgL);
    pb1 = *(const float4*)(BgL + 4 * GN);
    {
        unsigned* as = &As[arow * ASTR + akc];
        *(uint4*)as       = make_uint4(f2tf(pa0.x), f2tf(pa1.x), f2tf(pa0.y), f2tf(pa1.y));
        *(uint4*)(as + 4) = make_uint4(f2tf(pa0.z), f2tf(pa1.z), f2tf(pa0.w), f2tf(pa1.w));
        unsigned* bs = &Bs[bkkc * BCH + btb * BTR + bn4 * 2];
        *(uint4*)bs       = make_uint4(f2tf(pb0.x), f2tf(pb1.x), f2tf(pb0.y), f2tf(pb1.y));
        *(uint4*)(bs + 4) = make_uint4(f2tf(pb0.z), f2tf(pb1.z), f2tf(pb0.w), f2tf(pb1.w));
    }
    __syncthreads();

    const int NKT = GK / 16;   // 48
    int cur = 0;
#pragma unroll 1
    for (int kt = 0; kt < NKT; kt++) {
        if (kt + 1 < NKT) {
            const float* ag = Ag + (kt + 1) * 16;
            const float* bl = BgL + (size_t)(kt + 1) * 16 * GN;
            pa0 = *(const float4*)(ag);
            pa1 = *(const float4*)(ag + 4);
            pb0 = *(const float4*)(bl);
            pb1 = *(const float4*)(bl + 4 * GN);
        }

#pragma unroll
        for (int kk = 0; kk < 16; kk += 8) {
            const int kkc = kk >> 3;
            unsigned af[2][4], bf[8][2];
#pragma unroll
            for (int mi = 0; mi < 2; mi++) {
                const int r = wm * 32 + mi * 16 + g;
                uint2 q0 = *(const uint2*)&As[cur * 128 * ASTR + r * ASTR + kk + 2 * t];
                uint2 q1 = *(const uint2*)&As[cur * 128 * ASTR + (r + 8) * ASTR + kk + 2 * t];
                af[mi][0] = q0.x; af[mi][1] = q1.x;
                af[mi][2] = q0.y; af[mi][3] = q1.y;
            }
#pragma unroll
            for (int nj = 0; nj < 8; nj++) {
                const int c = wn * 64 + nj * 8 + g;
                uint2 qb = *(const uint2*)&Bs[cur * 2 * BCH + kkc * BCH + t * BTR + c * 2];
                bf[nj][0] = qb.x; bf[nj][1] = qb.y;
            }
#pragma unroll
            for (int mi = 0; mi < 2; mi++)
#pragma unroll
                for (int nj = 0; nj < 8; nj++)
                    mma_tf32(acc[mi][nj], af[mi], bf[nj]);
        }

        if (kt + 1 < NKT) {
            const int nxt = cur ^ 1;
            unsigned* as = &As[nxt * 128 * ASTR + arow * ASTR + akc];
            *(uint4*)as       = make_uint4(f2tf(pa0.x), f2tf(pa1.x), f2tf(pa0.y), f2tf(pa1.y));
            *(uint4*)(as + 4) = make_uint4(f2tf(pa0.z), f2tf(pa1.z), f2tf(pa0.w), f2tf(pa1.w));
            unsigned* bs = &Bs[nxt * 2 * BCH + bkkc * BCH + btb * BTR + bn4 * 2];
            *(uint4*)bs       = make_uint4(f2tf(pb0.x), f2tf(pb1.x), f2tf(pb0.y), f2tf(pb1.y));
            *(uint4*)(bs + 4) = make_uint4(f2tf(pb0.z), f2tf(pb1.z), f2tf(pb0.w), f2tf(pb1.w));
            __syncthreads();
            cur = nxt;
        }
    }

    const int row0 = by * 128 + wm * 32;
    const int col0 = bx * 128 + wn * 64;
#pragma unroll
    for (int mi = 0; mi < 2; mi++) {
#pragma unroll
        for (int nj = 0; nj < 8; nj++) {
            const int r = row0 + mi * 16 + g;
            const int c = col0 + nj * 8 + t * 2;
            float v0 = acc[mi][nj][0], v1 = acc[mi][nj][1];
            float v2 = acc[mi][nj][2], v3 = acc[mi][nj][3];
            if (MODE >= 1) {
                const float bb0 = bias[c], bb1 = bias[c + 1];
                v0 += bb0; v1 += bb1; v2 += bb0; v3 += bb1;
            }
            if (MODE == 1) {
                v0 = fmaxf(v0, 0.0f); v1 = fmaxf(v1, 0.0f);
                v2 = fmaxf(v2, 0.0f); v3 = fmaxf(v3, 0.0f);
            }
            if (MODE == 2) {
                const float* rr0 = g_ao + (size_t)r * GN + c;
                const float* rr1 = g_ao + (size_t)(r + 8) * GN + c;
                v0 += rr0[0]; v1 += rr0[1];
                v2 += rr1[0]; v3 += rr1[1];
            }
            *(float2*)(C + (size_t)r * GN + c)       = make_float2(v0, v1);
            *(float2*)(C + (size_t)(r + 8) * GN + c) = make_float2(v2, v3);
        }
    }
}

// Fused QKV projection: blockIdx.z selects {queries@Wq->g_q, keys@Wk->g_k,
// values@Wv->g_v}. 1152 CTAs -> tail wave amortized across all three GEMMs.
__global__ __launch_bounds__(256, 2)
void qkv_kernel(const float* __restrict__ qin, const float* __restrict__ kin,
                const float* __restrict__ vin, const float* __restrict__ Wq,
                const float* __restrict__ Wk, const float* __restrict__ Wv)
{
    __shared__ unsigned As[2][128 * ASTR];
    __shared__ unsigned Bs[2][2 * BCH];
    const int z = blockIdx.z;
    const float* A  = (z == 0) ? qin : (z == 1) ? kin : vin;
    const float* Bm = (z == 0) ? Wq  : (z == 1) ? Wk  : Wv;
    float* C        = (z == 0) ? g_q : (z == 1) ? g_k : g_v;
    gemm_body<0>(A, Bm, C, nullptr, &As[0][0], &Bs[0][0],
                 blockIdx.x, blockIdx.y);
}

// Single GEMM launches (serial chain after attention)
template<int ASEL, int CSEL, int MODE>
__global__ __launch_bounds__(256, 2)
void tgemm_kernel(const float* __restrict__ Bm, const float* __restrict__ bias)
{
    __shared__ unsigned As[2][128 * ASTR];
    __shared__ unsigned Bs[2][2 * BCH];
    const float* A = (ASEL == 1) ? g_att : (ASEL == 2) ? g_ao : g_f1;
    float* C = (CSEL == 3) ? g_ao : (CSEL == 4) ? g_f1 : g_y;
    gemm_body<MODE>(A, Bm, C, bias, &As[0][0], &Bs[0][0],
                    blockIdx.x, blockIdx.y);
}

// ---------------------------------------------------------------------------
// Tensor-core flash attention (tf32 mma), double-buffered K/V with register
// prefetch: LDG for tile kt+1 issued before tile kt's mmas, STS to alternate
// smem buffer, single barrier per tile.
// Block = (128 q rows, head h, batch b); 8 warps x 16 q rows.
// ---------------------------------------------------------------------------
#define BQ   128
#define BKT  64
#define QSTR 72
#define KSTR 72
#define VTR  136
#define VCH  (4 * VTR)    // 544
#define PSTR 68
#define KWORDS (BKT * KSTR)    // 4608
#define VWORDS (8 * VCH)       // 4352
#define ATTN_SMEM ((BQ*QSTR + 2*KWORDS + 2*VWORDS + BQ*PSTR) * 4)  // 143360 B

__global__ __launch_bounds__(256)
void attn_kernel() {
    extern __shared__ unsigned smu[];
    unsigned* Qs = smu;                       // [q][d-interleaved] stride 72
    unsigned* Ks = Qs + BQ * QSTR;            // 2 buffers
    unsigned* Vs = Ks + 2 * KWORDS;           // 2 buffers
    unsigned* Ps = Vs + 2 * VWORDS;           // per-warp [16][64] stride 68

    const int qt = blockIdx.x;
    const int h  = blockIdx.y;
    const int b  = blockIdx.z;
    const int tid  = threadIdx.x;
    const int warp = tid >> 5;
    const int lane = tid & 31;
    const int g = lane >> 2;
    const int t = lane & 3;
    const int R0 = warp * 16;
    unsigned* Pw = Ps + R0 * PSTR;

    const int valid = g_valid[b];
    const int nkt = (valid > 0) ? ((valid + BKT - 1) / BKT) : (SLK / BKT);

    const float* Qb = g_q + ((size_t)b * SLQ + qt * BQ) * DMODEL + h * DHEAD;
    const float* Kb = g_k + (size_t)b * SLK * DMODEL + h * DHEAD;
    const float* Vb = g_v + (size_t)b * SLK * DMODEL + h * DHEAD;

    // loader mappings
    const int kr0 = tid >> 3;            // K rows handled: kr0, kr0+32
    const int kc8 = tid & 7;
    const int vd8 = (tid & 7) * 8;
    const int vrp = tid >> 3;
    const int vkvc = vrp >> 2;
    const int vtt  = vrp & 3;

    // load Q tile: k-interleaved pairs, scaled by 1/8, tf32
#pragma unroll
    for (int it = 0; it < 4; it++) {
        int idx = it * 256 + tid;
        int r = idx >> 3, c8 = idx & 7;
        const float* p = Qb + (size_t)r * DMODEL + c8 * 8;
        float4 lo = *(const float4*)(p);
        float4 hi = *(const float4*)(p + 4);
        unsigned* q = &Qs[r * QSTR + c8 * 8];
        *(uint4*)q       = make_uint4(f2tf(lo.x * 0.125f), f2tf(hi.x * 0.125f),
                                      f2tf(lo.y * 0.125f), f2tf(hi.y * 0.125f));
        *(uint4*)(q + 4) = make_uint4(f2tf(lo.z * 0.125f), f2tf(hi.z * 0.125f),
                                      f2tf(lo.w * 0.125f), f2tf(hi.w * 0.125f));
    }

    float m_lo = -1e30f, m_hi = -1e30f, l_lo = 0.0f, l_hi = 0.0f;
    float oa[8][4];
#pragma unroll
    for (int nb = 0; nb < 8; nb++)
#pragma unroll
        for (int q = 0; q < 4; q++) oa[nb][q] = 0.0f;

    float4 kp[2][2], vp[4];

    // prologue: gmem-load tile 0, store to buffer 0
    {
        const float* p0 = Kb + (size_t)kr0 * DMODEL + kc8 * 8;
        kp[0][0] = *(const float4*)(p0);
        kp[0][1] = *(const float4*)(p0 + 4);
        const float* p1 = p0 + 32 * DMODEL;
        kp[1][0] = *(const float4*)(p1);
        kp[1][1] = *(const float4*)(p1 + 4);
        const float* pv0 = Vb + (size_t)(vkvc * 8 + vtt) * DMODEL + vd8;
        vp[0] = *(const float4*)(pv0);
        vp[1] = *(const float4*)(pv0 + 4);
        vp[2] = *(const float4*)(pv0 + 4 * DMODEL);
        vp[3] = *(const float4*)(pv0 + 4 * DMODEL + 4);
    }
#pragma unroll
    for (int it = 0; it < 2; it++) {
        unsigned* q = &Ks[(kr0 + it * 32) * KSTR + kc8 * 8];
        *(uint4*)q       = make_uint4(f2tf(kp[it][0].x), f2tf(kp[it][1].x),
                                      f2tf(kp[it][0].y), f2tf(kp[it][1].y));
        *(uint4*)(q + 4) = make_uint4(f2tf(kp[it][0].z), f2tf(kp[it][1].z),
                                      f2tf(kp[it][0].w), f2tf(kp[it][1].w));
    }
    {
        unsigned* vdst = &Vs[vkvc * VCH + vtt * VTR + vd8 * 2];
        *(uint4*)(vdst)      = make_uint4(f2tf(vp[0].x), f2tf(vp[2].x), f2tf(vp[0].y), f2tf(vp[2].y));
        *(uint4*)(vdst + 4)  = make_uint4(f2tf(vp[0].z), f2tf(vp[2].z), f2tf(vp[0].w), f2tf(vp[2].w));
        *(uint4*)(vdst + 8)  = make_uint4(f2tf(vp[1].x), f2tf(vp[3].x), f2tf(vp[1].y), f2tf(vp[3].y));
        *(uint4*)(vdst + 12) = make_uint4(f2tf(vp[1].z), f2tf(vp[3].z), f2tf(vp[1].w), f2tf(vp[3].w));
    }
    __syncthreads();

    int cur = 0;
#pragma unroll 1
    for (int kt = 0; kt < nkt; kt++) {
        // prefetch next tile into registers
        if (kt + 1 < nkt) {
            const float* p0 = Kb + (size_t)((kt + 1) * BKT + kr0) * DMODEL + kc8 * 8;
            kp[0][0] = *(const float4*)(p0);
            kp[0][1] = *(const float4*)(p0 + 4);
            const float* p1 = p0 + 32 * DMODEL;
            kp[1][0] = *(const float4*)(p1);
            kp[1][1] = *(const float4*)(p1 + 4);
            const float* pv0 = Vb + (size_t)((kt + 1) * BKT + vkvc * 8 + vtt) * DMODEL + vd8;
            vp[0] = *(const float4*)(pv0);
            vp[1] = *(const float4*)(pv0 + 4);
            vp[2] = *(const float4*)(pv0 + 4 * DMODEL);
            vp[3] = *(const float4*)(pv0 + 4 * DMODEL + 4);
        }

        const unsigned* Kc = Ks + cur * KWORDS;
        const unsigned* Vc = Vs + cur * VWORDS;

        // S = Q K^T  (64 mmas per warp)
        float sa[8][4];
#pragma unroll
        for (int nb = 0; nb < 8; nb++)
#pragma unroll
            for (int q = 0; q < 4; q++) sa[nb][q] = 0.0f;

#pragma unroll
        for (int kb = 0; kb < 8; kb++) {
            unsigned af[4];
            uint2 q0 = *(const uint2*)&Qs[(R0 + g) * QSTR + kb * 8 + 2 * t];
            uint2 q1 = *(const uint2*)&Qs[(R0 + g + 8) * QSTR + kb * 8 + 2 * t];
            af[0] = q0.x; af[1] = q1.x; af[2] = q0.y; af[3] = q1.y;
#pragma unroll
            for (int nb = 0; nb < 8; nb++) {
                unsigned bf[2];
                uint2 qk = *(const uint2*)&Kc[(nb * 8 + g) * KSTR + kb * 8 + 2 * t];
                bf[0] = qk.x; bf[1] = qk.y;
                mma_tf32(sa[nb], af, bf);
            }
        }

        // mask columns >= valid
        const int cbase = kt * BKT + 2 * t;
#pragma unroll
        for (int nb = 0; nb < 8; nb++) {
            const int c0 = cbase + nb * 8;
            if (c0     >= valid) { sa[nb][0] = -1e6f; sa[nb][2] = -1e6f; }
            if (c0 + 1 >= valid) { sa[nb][1] = -1e6f; sa[nb][3] = -1e6f; }
        }

        // online softmax (rows g and g+8 of this warp's 16)
        float tm_lo = -1e30f, tm_hi = -1e30f;
#pragma unroll
        for (int nb = 0; nb < 8; nb++) {
            tm_lo = fmaxf(tm_lo, fmaxf(sa[nb][0], sa[nb][1]));
            tm_hi = fmaxf(tm_hi, fmaxf(sa[nb][2], sa[nb][3]));
        }
#pragma unroll
        for (int off = 1; off < 4; off <<= 1) {
            tm_lo = fmaxf(tm_lo, __shfl_xor_sync(0xffffffffu, tm_lo, off));
            tm_hi = fmaxf(tm_hi, __shfl_xor_sync(0xffffffffu, tm_hi, off));
        }
        const float mn_lo = fmaxf(m_lo, tm_lo);
        const float mn_hi = fmaxf(m_hi, tm_hi);
        const float corr_lo = __expf(m_lo - mn_lo);
        const float corr_hi = __expf(m_hi - mn_hi);
        m_lo = mn_lo; m_hi = mn_hi;

        float ts_lo = 0.0f, ts_hi = 0.0f;
#pragma unroll
        for (int nb = 0; nb < 8; nb++) {
            float p0 = __expf(sa[nb][0] - mn_lo);
            float p1 = __expf(sa[nb][1] - mn_lo);
            float p2 = __expf(sa[nb][2] - mn_hi);
            float p3 = __expf(sa[nb][3] - mn_hi);
            ts_lo += p0 + p1;
            ts_hi += p2 + p3;
            *(uint2*)&Pw[g * PSTR + nb * 8 + 2 * t] =
                make_uint2(f2tf(p0), f2tf(p1));
            *(uint2*)&Pw[(g + 8) * PSTR + nb * 8 + 2 * t] =
                make_uint2(f2tf(p2), f2tf(p3));
        }
#pragma unroll
        for (int off = 1; off < 4; off <<= 1) {
            ts_lo += __shfl_xor_sync(0xffffffffu, ts_lo, off);
            ts_hi += __shfl_xor_sync(0xffffffffu, ts_hi, off);
        }
        l_lo = l_lo * corr_lo + ts_lo;
        l_hi = l_hi * corr_hi + ts_hi;
#pragma unroll
        for (int nb = 0; nb < 8; nb++) {
            oa[nb][0] *= corr_lo; oa[nb][1] *= corr_lo;
            oa[nb][2] *= corr_hi; oa[nb][3] *= corr_hi;
        }
        __syncwarp();

        // O += P V  (64 mmas per warp)
#pragma unroll
        for (int kb = 0; kb < 8; kb++) {
            unsigned af[4];
            const unsigned* pp = &Pw[g * PSTR + kb * 8 + t];
            af[0] = pp[0];
            af[1] = pp[8 * PSTR];
            af[2] = pp[4];
            af[3] = pp[8 * PSTR + 4];
#pragma unroll
            for (int nb = 0; nb < 8; nb++) {
                unsigned bf[2];
                uint2 qv = *(const uint2*)&Vc[kb * VCH + t * VTR + (nb * 8 + g) * 2];
                bf[0] = qv.x; bf[1] = qv.y;
                mma_tf32(oa[nb], af, bf);
            }
        }
        __syncwarp();   // Pw reads done before next tile's softmax overwrites

        // store prefetched tile into the other buffer, single barrier
        if (kt + 1 < nkt) {
            const int nxt = cur ^ 1;
            unsigned* Kn = Ks + nxt * KWORDS;
            unsigned* Vn = Vs + nxt * VWORDS;
#pragma unroll
            for (int it = 0; it < 2; it++) {
                unsigned* q = &Kn[(kr0 + it * 32) * KSTR + kc8 * 8];
                *(uint4*)q       = make_uint4(f2tf(kp[it][0].x), f2tf(kp[it][1].x),
                                              f2tf(kp[it][0].y), f2tf(kp[it][1].y));
                *(uint4*)(q + 4) = make_uint4(f2tf(kp[it][0].z), f2tf(kp[it][1].z),
                                              f2tf(kp[it][0].w), f2tf(kp[it][1].w));
            }
            unsigned* vdst = &Vn[vkvc * VCH + vtt * VTR + vd8 * 2];
            *(uint4*)(vdst)      = make_uint4(f2tf(vp[0].x), f2tf(vp[2].x), f2tf(vp[0].y), f2tf(vp[2].y));
            *(uint4*)(vdst + 4)  = make_uint4(f2tf(vp[0].z), f2tf(vp[2].z), f2tf(vp[0].w), f2tf(vp[2].w));
            *(uint4*)(vdst + 8)  = make_uint4(f2tf(vp[1].x), f2tf(vp[3].x), f2tf(vp[1].y), f2tf(vp[3].y));
            *(uint4*)(vdst + 12) = make_uint4(f2tf(vp[1].z), f2tf(vp[3].z), f2tf(vp[1].w), f2tf(vp[3].w));
            __syncthreads();
            cur = nxt;
        }
    }

    // epilogue
    const float inv_lo = 1.0f / l_lo;
    const float inv_hi = 1.0f / l_hi;
    const int row_lo = qt * BQ + R0 + g;
    float* Ob = g_att + ((size_t)b * SLQ) * DMODEL + h * DHEAD;
#pragma unroll
    for (int nb = 0; nb < 8; nb++) {
        const int c = nb * 8 + 2 * t;
        *(float2*)(Ob + (size_t)row_lo * DMODEL + c) =
            make_float2(oa[nb][0] * inv_lo, oa[nb][1] * inv_lo);
        *(float2*)(Ob + (size_t)(row_lo + 8) * DMODEL + c) =
            make_float2(oa[nb][2] * inv_hi, oa[nb][3] * inv_hi);
    }
}

// ---------------------------------------------------------------------------
// LayerNorm over g_y rows -> out
// ---------------------------------------------------------------------------
__global__ __launch_bounds__(256)
void ln_kernel(const float* __restrict__ gamma,
               const float* __restrict__ beta,
               float* __restrict__ out)
{
    __shared__ float rs[256], rs2[256];
    const int row = blockIdx.x;
    const float* y = g_y + (size_t)row * DMODEL;
    float v[3], s = 0.0f, s2 = 0.0f;
#pragma unroll
    for (int t = 0; t < 3; t++) {
        v[t] = y[threadIdx.x + t * 256];
        s += v[t]; s2 += v[t] * v[t];
    }
    rs[threadIdx.x] = s; rs2[threadIdx.x] = s2;
    __syncthreads();
    for (int st = 128; st > 0; st >>= 1) {
        if (threadIdx.x < st) {
            rs[threadIdx.x]  += rs[threadIdx.x + st];
            rs2[threadIdx.x] += rs2[threadIdx.x + st];
        }
        __syncthreads();
    }
    const float mean = rs[0] * (1.0f / DMODEL);
    const float var  = rs2[0] * (1.0f / DMODEL) - mean * mean;
    const float inv  = rsqrtf(var + 1e-5f);
#pragma unroll
    for (int t = 0; t < 3; t++) {
        int col = threadIdx.x + t * 256;
        out[(size_t)row * DMODEL + col] = (v[t] - mean) * inv * gamma[col] + beta[col];
    }
}

// ---------------------------------------------------------------------------
// Launch
// ---------------------------------------------------------------------------
extern "C" void kernel_launch(void* const* d_in, const int* in_sizes, int n_in,
                              void* d_out, int out_size)
{
    (void)in_sizes; (void)n_in; (void)out_size;
    const float* queries = (const float*)d_in[0];
    const float* keys    = (const float*)d_in[1];
    const float* values  = (const float*)d_in[2];
    const int*   mask    = (const int*)  d_in[3];
    const float* Wq = (const float*)d_in[4];
    const float* Wk = (const float*)d_in[5];
    const float* Wv = (const float*)d_in[6];
    const float* Wo = (const float*)d_in[7];
    const float* W1 = (const float*)d_in[8];
    const float* b1 = (const float*)d_in[9];
    const float* W2 = (const float*)d_in[10];
    const float* b2 = (const float*)d_in[11];
    const float* lg = (const float*)d_in[12];
    const float* lb = (const float*)d_in[13];
    float* out = (float*)d_out;

    valid_kernel<<<BATCH, 256>>>(mask);

    qkv_kernel<<<dim3(GN / 128, MROWS / 128, 3), 256>>>(
        queries, keys, values, Wq, Wk, Wv);

    cudaFuncSetAttribute(attn_kernel,
                         cudaFuncAttributeMaxDynamicSharedMemorySize,
                         (int)ATTN_SMEM);
    attn_kernel<<<dim3(SLQ / BQ, NHEAD, BATCH), 256, ATTN_SMEM>>>();

    dim3 ggrid(GN / 128, MROWS / 128);   // (6, 64)
    tgemm_kernel<1, 3, 0><<<ggrid, 256>>>(Wo, nullptr);  // att_out
    tgemm_kernel<2, 4, 1><<<ggrid, 256>>>(W1, b1);       // relu(ffn1)
    tgemm_kernel<3, 5, 2><<<ggrid, 256>>>(W2, b2);       // y = ffn2 + att_out

    ln_kernel<<<MROWS, 256>>>(lg, lb, out);
}

// round 16
// speedup vs baseline: 1.5519x; 1.5519x over previous
#include <cuda_runtime.h>
#include <math.h>

// Problem constants
#define BATCH  4
#define SLQ    2048
#define SLK    2048
#define DMODEL 768
#define NHEAD  12
#define DHEAD  64
#define MROWS  (BATCH * SLQ)   // 8192

// ---------------------------------------------------------------------------
// Scratch (device globals; no allocation allowed)
// ---------------------------------------------------------------------------
__device__ float g_q  [(size_t)MROWS * DMODEL];
__device__ float g_k  [(size_t)BATCH * SLK * DMODEL];
__device__ float g_v  [(size_t)BATCH * SLK * DMODEL];
__device__ float g_att[(size_t)MROWS * DMODEL];
__device__ float g_ao [(size_t)MROWS * DMODEL];
__device__ float g_f1 [(size_t)MROWS * DMODEL];
__device__ float g_y  [(size_t)MROWS * DMODEL];
__device__ int   g_valid[BATCH];

// ---------------------------------------------------------------------------
// valid_lens[b] = count of nonzero mask entries in row b
// ---------------------------------------------------------------------------
__global__ void valid_kernel(const int* __restrict__ mask) {
    __shared__ int red[256];
    int b = blockIdx.x;
    int cnt = 0;
    for (int i = threadIdx.x; i < SLK; i += 256)
        cnt += (mask[b * SLK + i] != 0) ? 1 : 0;
    red[threadIdx.x] = cnt;
    __syncthreads();
    for (int s = 128; s > 0; s >>= 1) {
        if (threadIdx.x < s) red[threadIdx.x] += red[threadIdx.x + s];
        __syncthreads();
    }
    if (threadIdx.x == 0) g_valid[b] = red[0];
}

// ---------------------------------------------------------------------------
// TF32 mma helpers
// ---------------------------------------------------------------------------
__device__ __forceinline__ unsigned f2tf(float f) {
    unsigned u;
    asm("cvt.rna.tf32.f32 %0, %1;" : "=r"(u) : "f"(f));
    return u;
}

__device__ __forceinline__ void mma_tf32(float c[4],
                                         const unsigned a[4],
                                         const unsigned b[2]) {
    asm volatile(
        "mma.sync.aligned.m16n8k8.row.col.f32.tf32.tf32.f32 "
        "{%0,%1,%2,%3}, {%4,%5,%6,%7}, {%8,%9}, {%0,%1,%2,%3};"
        : "+f"(c[0]), "+f"(c[1]), "+f"(c[2]), "+f"(c[3])
        : "r"(a[0]), "r"(a[1]), "r"(a[2]), "r"(a[3]),
          "r"(b[0]), "r"(b[1]));
}

// ---------------------------------------------------------------------------
// TF32 tensor-core GEMM core (128x128 tile, BK=16 double-buffered, 8 warps).
// A smem: per-row k-interleaved pairs (k, k+4), stride 24 -> a-frag LDS.64.
// B smem: [kchunk][t][n][pair], t-row stride 264 -> b-frag LDS.64.
// Shared buffers passed as 2D array references so ptxas keeps the buffer
// flip as pointer select (the R12 flat-index version regressed 99->141us).
// MODE: 0=plain, 1=+bias,ReLU, 2=+bias,+residual(g_ao)
// ---------------------------------------------------------------------------
#define GK DMODEL
#define GN DMODEL
#define ASTR 24
#define BTR  264
#define BCH  (4 * BTR)   // 1056

template<int MODE>
__device__ __forceinline__ void gemm_body(const float* __restrict__ A,
                                          const float* __restrict__ Bm,
                                          float* __restrict__ C,
                                          const float* __restrict__ bias,
                                          unsigned (&As)[2][128 * ASTR],
                                          unsigned (&Bs)[2][2 * BCH],
                                          int bx, int by)
{
    const int tid = threadIdx.x;
    const int warp = tid >> 5;
    const int lane = tid & 31;
    const int wm = warp >> 1;
    const int wn = warp & 1;
    const int g  = lane >> 2;
    const int t  = lane & 3;

    float acc[2][8][4];
#pragma unroll
    for (int mi = 0; mi < 2; mi++)
#pragma unroll
        for (int nj = 0; nj < 8; nj++)
#pragma unroll
            for (int q = 0; q < 4; q++) acc[mi][nj][q] = 0.0f;

    const int arow = tid >> 1;
    const int akc  = (tid & 1) * 8;
    const int bn4  = (tid & 31) * 4;
    const int bkrw = tid >> 5;
    const int bkkc = bkrw >> 2;
    const int btb  = bkrw & 3;

    const float* Ag  = A  + (size_t)(by * 128 + arow) * GK + akc;
    const float* BgL = Bm + (size_t)(bkkc * 8 + btb) * GN + bx * 128 + bn4;

    float4 pa0, pa1, pb0, pb1;

    pa0 = *(const float4*)(Ag);
    pa1 = *(const float4*)(Ag + 4);
    pb0 = *(const float4*)(BgL);
    pb1 = *(const float4*)(BgL + 4 * GN);
    {
        unsigned* as = &As[0][arow * ASTR + akc];
        *(uint4*)as       = make_uint4(f2tf(pa0.x), f2tf(pa1.x), f2tf(pa0.y), f2tf(pa1.y));
        *(uint4*)(as + 4) = make_uint4(f2tf(pa0.z), f2tf(pa1.z), f2tf(pa0.w), f2tf(pa1.w));
        unsigned* bs = &Bs[0][bkkc * BCH + btb * BTR + bn4 * 2];
        *(uint4*)bs       = make_uint4(f2tf(pb0.x), f2tf(pb1.x), f2tf(pb0.y), f2tf(pb1.y));
        *(uint4*)(bs + 4) = make_uint4(f2tf(pb0.z), f2tf(pb1.z), f2tf(pb0.w), f2tf(pb1.w));
    }
    __syncthreads();

    const int NKT = GK / 16;   // 48
    int cur = 0;
#pragma unroll 1
    for (int kt = 0; kt < NKT; kt++) {
        if (kt + 1 < NKT) {
            const float* ag = Ag + (kt + 1) * 16;
            const float* bl = BgL + (size_t)(kt + 1) * 16 * GN;
            pa0 = *(const float4*)(ag);
            pa1 = *(const float4*)(ag + 4);
            pb0 = *(const float4*)(bl);
            pb1 = *(const float4*)(bl + 4 * GN);
        }

#pragma unroll
        for (int kk = 0; kk < 16; kk += 8) {
            const int kkc = kk >> 3;
            unsigned af[2][4], bf[8][2];
#pragma unroll
            for (int mi = 0; mi < 2; mi++) {
                const int r = wm * 32 + mi * 16 + g;
                uint2 q0 = *(const uint2*)&As[cur][r * ASTR + kk + 2 * t];
                uint2 q1 = *(const uint2*)&As[cur][(r + 8) * ASTR + kk + 2 * t];
                af[mi][0] = q0.x; af[mi][1] = q1.x;
                af[mi][2] = q0.y; af[mi][3] = q1.y;
            }
#pragma unroll
            for (int nj = 0; nj < 8; nj++) {
                const int c = wn * 64 + nj * 8 + g;
                uint2 qb = *(const uint2*)&Bs[cur][kkc * BCH + t * BTR + c * 2];
                bf[nj][0] = qb.x; bf[nj][1] = qb.y;
            }
#pragma unroll
            for (int mi = 0; mi < 2; mi++)
#pragma unroll
                for (int nj = 0; nj < 8; nj++)
                    mma_tf32(acc[mi][nj], af[mi], bf[nj]);
        }

        if (kt + 1 < NKT) {
            const int nxt = cur ^ 1;
            unsigned* as = &As[nxt][arow * ASTR + akc];
            *(uint4*)as       = make_uint4(f2tf(pa0.x), f2tf(pa1.x), f2tf(pa0.y), f2tf(pa1.y));
            *(uint4*)(as + 4) = make_uint4(f2tf(pa0.z), f2tf(pa1.z), f2tf(pa0.w), f2tf(pa1.w));
            unsigned* bs = &Bs[nxt][bkkc * BCH + btb * BTR + bn4 * 2];
            *(uint4*)bs       = make_uint4(f2tf(pb0.x), f2tf(pb1.x), f2tf(pb0.y), f2tf(pb1.y));
            *(uint4*)(bs + 4) = make_uint4(f2tf(pb0.z), f2tf(pb1.z), f2tf(pb0.w), f2tf(pb1.w));
            __syncthreads();
            cur = nxt;
        }
    }

    const int row0 = by * 128 + wm * 32;
    const int col0 = bx * 128 + wn * 64;
#pragma unroll
    for (int mi = 0; mi < 2; mi++) {
#pragma unroll
        for (int nj = 0; nj < 8; nj++) {
            const int r = row0 + mi * 16 + g;
            const int c = col0 + nj * 8 + t * 2;
            float v0 = acc[mi][nj][0], v1 = acc[mi][nj][1];
            float v2 = acc[mi][nj][2], v3 = acc[mi][nj][3];
            if (MODE >= 1) {
                const float bb0 = bias[c], bb1 = bias[c + 1];
                v0 += bb0; v1 += bb1; v2 += bb0; v3 += bb1;
            }
            if (MODE == 1) {
                v0 = fmaxf(v0, 0.0f); v1 = fmaxf(v1, 0.0f);
                v2 = fmaxf(v2, 0.0f); v3 = fmaxf(v3, 0.0f);
            }
            if (MODE == 2) {
                const float* rr0 = g_ao + (size_t)r * GN + c;
                const float* rr1 = g_ao + (size_t)(r + 8) * GN + c;
                v0 += rr0[0]; v1 += rr0[1];
                v2 += rr1[0]; v3 += rr1[1];
            }
            *(float2*)(C + (size_t)r * GN + c)       = make_float2(v0, v1);
            *(float2*)(C + (size_t)(r + 8) * GN + c) = make_float2(v2, v3);
        }
    }
}

// Fused QKV projection: blockIdx.z selects {queries@Wq->g_q, keys@Wk->g_k,
// values@Wv->g_v}. 1152 CTAs -> tail wave amortized across all three GEMMs.
__global__ __launch_bounds__(256, 2)
void qkv_kernel(const float* __restrict__ qin, const float* __restrict__ kin,
                const float* __restrict__ vin, const float* __restrict__ Wq,
                const float* __restrict__ Wk, const float* __restrict__ Wv)
{
    __shared__ unsigned As[2][128 * ASTR];
    __shared__ unsigned Bs[2][2 * BCH];
    const int z = blockIdx.z;
    const float* A  = (z == 0) ? qin : (z == 1) ? kin : vin;
    const float* Bm = (z == 0) ? Wq  : (z == 1) ? Wk  : Wv;
    float* C        = (z == 0) ? g_q : (z == 1) ? g_k : g_v;
    gemm_body<0>(A, Bm, C, nullptr, As, Bs, blockIdx.x, blockIdx.y);
}

// Serial GEMM chain after attention
template<int ASEL, int CSEL, int MODE>
__global__ __launch_bounds__(256, 2)
void tgemm_kernel(const float* __restrict__ Bm, const float* __restrict__ bias)
{
    __shared__ unsigned As[2][128 * ASTR];
    __shared__ unsigned Bs[2][2 * BCH];
    const float* A = (ASEL == 1) ? g_att : (ASEL == 2) ? g_ao : g_f1;
    float* C = (CSEL == 3) ? g_ao : (CSEL == 4) ? g_f1 : g_y;
    gemm_body<MODE>(A, Bm, C, bias, As, Bs, blockIdx.x, blockIdx.y);
}

// ---------------------------------------------------------------------------
// Tensor-core flash attention (tf32 mma) — R9 version (single-buffered).
// Block = (128 q rows, head h, batch b); 8 warps x 16 q rows.
// Q/K smem: per-row k-interleaved pairs, stride 72 -> LDS.64 frags.
// V smem: [kvchunk][t][d][pair], t-row stride 136 -> LDS.64 frags.
// P staged per-warp ([r][c], stride 68).
// K tiles fully beyond valid_len skipped (exact).
// ---------------------------------------------------------------------------
#define BQ   128
#define BKT  64
#define QSTR 72
#define KSTR 72
#define VTR  136
#define VCH  (4 * VTR)    // 544
#define PSTR 68
#define ATTN_SMEM ((BQ*QSTR + BKT*KSTR + 8*VCH + BQ*PSTR) * 4)  // 107520 B

__global__ __launch_bounds__(256)
void attn_kernel() {
    extern __shared__ unsigned smu[];
    unsigned* Qs = smu;                    // [q][d-interleaved] stride 72
    unsigned* Ks = Qs + BQ * QSTR;         // [c][d-interleaved] stride 72
    unsigned* Vs = Ks + BKT * KSTR;        // [kvc][t][d][pair]
    unsigned* Ps = Vs + 8 * VCH;           // per-warp [16][64] stride 68

    const int qt = blockIdx.x;
    const int h  = blockIdx.y;
    const int b  = blockIdx.z;
    const int tid  = threadIdx.x;
    const int warp = tid >> 5;
    const int lane = tid & 31;
    const int g = lane >> 2;
    const int t = lane & 3;
    const int R0 = warp * 16;
    unsigned* Pw = Ps + R0 * PSTR;

    const int valid = g_valid[b];
    const int nkt = (valid > 0) ? ((valid + BKT - 1) / BKT) : (SLK / BKT);

    const float* Qb = g_q + ((size_t)b * SLQ + qt * BQ) * DMODEL + h * DHEAD;
    const float* Kb = g_k + (size_t)b * SLK * DMODEL + h * DHEAD;
    const float* Vb = g_v + (size_t)b * SLK * DMODEL + h * DHEAD;

    // load Q tile: k-interleaved pairs, scaled by 1/8, tf32
#pragma unroll
    for (int it = 0; it < 4; it++) {
        int idx = it * 256 + tid;
        int r = idx >> 3, c8 = idx & 7;
        const float* p = Qb + (size_t)r * DMODEL + c8 * 8;
        float4 lo = *(const float4*)(p);
        float4 hi = *(const float4*)(p + 4);
        unsigned* q = &Qs[r * QSTR + c8 * 8];
        *(uint4*)q       = make_uint4(f2tf(lo.x * 0.125f), f2tf(hi.x * 0.125f),
                                      f2tf(lo.y * 0.125f), f2tf(hi.y * 0.125f));
        *(uint4*)(q + 4) = make_uint4(f2tf(lo.z * 0.125f), f2tf(hi.z * 0.125f),
                                      f2tf(lo.w * 0.125f), f2tf(hi.w * 0.125f));
    }

    float m_lo = -1e30f, m_hi = -1e30f, l_lo = 0.0f, l_hi = 0.0f;
    float oa[8][4];
#pragma unroll
    for (int nb = 0; nb < 8; nb++)
#pragma unroll
        for (int q = 0; q < 4; q++) oa[nb][q] = 0.0f;

    // V loader mapping
    const int vd8 = (tid & 7) * 8;
    const int vrp = tid >> 3;
    const int vkvc = vrp >> 2;
    const int vtt  = vrp & 3;

#pragma unroll 1
    for (int kt = 0; kt < nkt; kt++) {
        __syncthreads();   // prev-tile K/V reads complete (also covers Q init)

        // K tile: k-interleaved rows
#pragma unroll
        for (int it = 0; it < 2; it++) {
            int idx = it * 256 + tid;
            int r = idx >> 3, c8 = idx & 7;
            const float* p = Kb + (size_t)(kt * BKT + r) * DMODEL + c8 * 8;
            float4 lo = *(const float4*)(p);
            float4 hi = *(const float4*)(p + 4);
            unsigned* q = &Ks[r * KSTR + c8 * 8];
            *(uint4*)q       = make_uint4(f2tf(lo.x), f2tf(hi.x), f2tf(lo.y), f2tf(hi.y));
            *(uint4*)(q + 4) = make_uint4(f2tf(lo.z), f2tf(hi.z), f2tf(lo.w), f2tf(hi.w));
        }
        // V tile: [kvc][t][d][pair]; thread reads rows kv0, kv0+4
        {
            const float* p0 = Vb + (size_t)(kt * BKT + vkvc * 8 + vtt) * DMODEL + vd8;
            const float* p1 = p0 + 4 * DMODEL;
            float4 lo0 = *(const float4*)(p0);
            float4 lo1 = *(const float4*)(p0 + 4);
            float4 hi0 = *(const float4*)(p1);
            float4 hi1 = *(const float4*)(p1 + 4);
            unsigned* vdst = &Vs[vkvc * VCH + vtt * VTR + vd8 * 2];
            *(uint4*)(vdst)      = make_uint4(f2tf(lo0.x), f2tf(hi0.x), f2tf(lo0.y), f2tf(hi0.y));
            *(uint4*)(vdst + 4)  = make_uint4(f2tf(lo0.z), f2tf(hi0.z), f2tf(lo0.w), f2tf(hi0.w));
            *(uint4*)(vdst + 8)  = make_uint4(f2tf(lo1.x), f2tf(hi1.x), f2tf(lo1.y), f2tf(hi1.y));
            *(uint4*)(vdst + 12) = make_uint4(f2tf(lo1.z), f2tf(hi1.z), f2tf(lo1.w), f2tf(hi1.w));
        }
        __syncthreads();

        // S = Q K^T  (64 mmas per warp)
        float sa[8][4];
#pragma unroll
        for (int nb = 0; nb < 8; nb++)
#pragma unroll
            for (int q = 0; q < 4; q++) sa[nb][q] = 0.0f;

#pragma unroll
        for (int kb = 0; kb < 8; kb++) {
            unsigned af[4];
            uint2 q0 = *(const uint2*)&Qs[(R0 + g) * QSTR + kb * 8 + 2 * t];
            uint2 q1 = *(const uint2*)&Qs[(R0 + g + 8) * QSTR + kb * 8 + 2 * t];
            af[0] = q0.x; af[1] = q1.x; af[2] = q0.y; af[3] = q1.y;
#pragma unroll
            for (int nb = 0; nb < 8; nb++) {
                unsigned bf[2];
                uint2 qk = *(const uint2*)&Ks[(nb * 8 + g) * KSTR + kb * 8 + 2 * t];
                bf[0] = qk.x; bf[1] = qk.y;
                mma_tf32(sa[nb], af, bf);
            }
        }

        // mask columns >= valid
        const int cbase = kt * BKT + 2 * t;
#pragma unroll
        for (int nb = 0; nb < 8; nb++) {
            const int c0 = cbase + nb * 8;
            if (c0     >= valid) { sa[nb][0] = -1e6f; sa[nb][2] = -1e6f; }
            if (c0 + 1 >= valid) { sa[nb][1] = -1e6f; sa[nb][3] = -1e6f; }
        }

        // online softmax (rows g and g+8 of this warp's 16)
        float tm_lo = -1e30f, tm_hi = -1e30f;
#pragma unroll
        for (int nb = 0; nb < 8; nb++) {
            tm_lo = fmaxf(tm_lo, fmaxf(sa[nb][0], sa[nb][1]));
            tm_hi = fmaxf(tm_hi, fmaxf(sa[nb][2], sa[nb][3]));
        }
#pragma unroll
        for (int off = 1; off < 4; off <<= 1) {
            tm_lo = fmaxf(tm_lo, __shfl_xor_sync(0xffffffffu, tm_lo, off));
            tm_hi = fmaxf(tm_hi, __shfl_xor_sync(0xffffffffu, tm_hi, off));
        }
        const float mn_lo = fmaxf(m_lo, tm_lo);
        const float mn_hi = fmaxf(m_hi, tm_hi);
        const float corr_lo = __expf(m_lo - mn_lo);
        const float corr_hi = __expf(m_hi - mn_hi);
        m_lo = mn_lo; m_hi = mn_hi;

        float ts_lo = 0.0f, ts_hi = 0.0f;
#pragma unroll
        for (int nb = 0; nb < 8; nb++) {
            float p0 = __expf(sa[nb][0] - mn_lo);
            float p1 = __expf(sa[nb][1] - mn_lo);
            float p2 = __expf(sa[nb][2] - mn_hi);
            float p3 = __expf(sa[nb][3] - mn_hi);
            ts_lo += p0 + p1;
            ts_hi += p2 + p3;
            *(uint2*)&Pw[g * PSTR + nb * 8 + 2 * t] =
                make_uint2(f2tf(p0), f2tf(p1));
            *(uint2*)&Pw[(g + 8) * PSTR + nb * 8 + 2 * t] =
                make_uint2(f2tf(p2), f2tf(p3));
        }
#pragma unroll
        for (int off = 1; off < 4; off <<= 1) {
            ts_lo += __shfl_xor_sync(0xffffffffu, ts_lo, off);
            ts_hi += __shfl_xor_sync(0xffffffffu, ts_hi, off);
        }
        l_lo = l_lo * corr_lo + ts_lo;
        l_hi = l_hi * corr_hi + ts_hi;
#pragma unroll
        for (int nb = 0; nb < 8; nb++) {
            oa[nb][0] *= corr_lo; oa[nb][1] *= corr_lo;
            oa[nb][2] *= corr_hi; oa[nb][3] *= corr_hi;
        }
        __syncwarp();

        // O += P V  (64 mmas per warp)
#pragma unroll
        for (int kb = 0; kb < 8; kb++) {
            unsigned af[4];
            const unsigned* pp = &Pw[g * PSTR + kb * 8 + t];
            af[0] = pp[0];
            af[1] = pp[8 * PSTR];
            af[2] = pp[4];
            af[3] = pp[8 * PSTR + 4];
#pragma unroll
            for (int nb = 0; nb < 8; nb++) {
                unsigned bf[2];
                uint2 qv = *(const uint2*)&Vs[kb * VCH + t * VTR + (nb * 8 + g) * 2];
                bf[0] = qv.x; bf[1] = qv.y;
                mma_tf32(oa[nb], af, bf);
            }
        }
        __syncwarp();   // Pw reads done before next tile's softmax overwrites
    }

    // epilogue
    const float inv_lo = 1.0f / l_lo;
    const float inv_hi = 1.0f / l_hi;
    const int row_lo = qt * BQ + R0 + g;
    float* Ob = g_att + ((size_t)b * SLQ) * DMODEL + h * DHEAD;
#pragma unroll
    for (int nb = 0; nb < 8; nb++) {
        const int c = nb * 8 + 2 * t;
        *(float2*)(Ob + (size_t)row_lo * DMODEL + c) =
            make_float2(oa[nb][0] * inv_lo, oa[nb][1] * inv_lo);
        *(float2*)(Ob + (size_t)(row_lo + 8) * DMODEL + c) =
            make_float2(oa[nb][2] * inv_hi, oa[nb][3] * inv_hi);
    }
}

// ---------------------------------------------------------------------------
// LayerNorm over g_y rows -> out
// ---------------------------------------------------------------------------
__global__ __launch_bounds__(256)
void ln_kernel(const float* __restrict__ gamma,
               const float* __restrict__ beta,
               float* __restrict__ out)
{
    __shared__ float rs[256], rs2[256];
    const int row = blockIdx.x;
    const float* y = g_y + (size_t)row * DMODEL;
    float v[3], s = 0.0f, s2 = 0.0f;
#pragma unroll
    for (int t = 0; t < 3; t++) {
        v[t] = y[threadIdx.x + t * 256];
        s += v[t]; s2 += v[t] * v[t];
    }
    rs[threadIdx.x] = s; rs2[threadIdx.x] = s2;
    __syncthreads();
    for (int st = 128; st > 0; st >>= 1) {
        if (threadIdx.x < st) {
            rs[threadIdx.x]  += rs[threadIdx.x + st];
            rs2[threadIdx.x] += rs2[threadIdx.x + st];
        }
        __syncthreads();
    }
    const float mean = rs[0] * (1.0f / DMODEL);
    const float var  = rs2[0] * (1.0f / DMODEL) - mean * mean;
    const float inv  = rsqrtf(var + 1e-5f);
#pragma unroll
    for (int t = 0; t < 3; t++) {
        int col = threadIdx.x + t * 256;
        out[(size_t)row * DMODEL + col] = (v[t] - mean) * inv * gamma[col] + beta[col];
    }
}

// ---------------------------------------------------------------------------
// Launch
// ---------------------------------------------------------------------------
extern "C" void kernel_launch(void* const* d_in, const int* in_sizes, int n_in,
                              void* d_out, int out_size)
{
    (void)in_sizes; (void)n_in; (void)out_size;
    const float* queries = (const float*)d_in[0];
    const float* keys    = (const float*)d_in[1];
    const float* values  = (const float*)d_in[2];
    const int*   mask    = (const int*)  d_in[3];
    const float* Wq = (const float*)d_in[4];
    const float* Wk = (const float*)d_in[5];
    const float* Wv = (const float*)d_in[6];
    const float* Wo = (const float*)d_in[7];
    const float* W1 = (const float*)d_in[8];
    const float* b1 = (const float*)d_in[9];
    const float* W2 = (const float*)d_in[10];
    const float* b2 = (const float*)d_in[11];
    const float* lg = (const float*)d_in[12];
    const float* lb = (const float*)d_in[13];
    float* out = (float*)d_out;

    valid_kernel<<<BATCH, 256>>>(mask);

    qkv_kernel<<<dim3(GN / 128, MROWS / 128, 3), 256>>>(
        queries, keys, values, Wq, Wk, Wv);

    cudaFuncSetAttribute(attn_kernel,
                         cudaFuncAttributeMaxDynamicSharedMemorySize,
                         (int)ATTN_SMEM);
    attn_kernel<<<dim3(SLQ / BQ, NHEAD, BATCH), 256, ATTN_SMEM>>>();

    dim3 ggrid(GN / 128, MROWS / 128);   // (6, 64)
    tgemm_kernel<1, 3, 0><<<ggrid, 256>>>(Wo, nullptr);  // att_out
    tgemm_kernel<2, 4, 1><<<ggrid, 256>>>(W1, b1);       // relu(ffn1)
    tgemm_kernel<3, 5, 2><<<ggrid, 256>>>(W2, b2);       // y = ffn2 + att_out

    ln_kernel<<<MROWS, 256>>>(lg, lb, out);
}

// round 17
// speedup vs baseline: 1.5869x; 1.0226x over previous
#include <cuda_runtime.h>
#include <math.h>

// Problem constants
#define BATCH  4
#define SLQ    2048
#define SLK    2048
#define DMODEL 768
#define NHEAD  12
#define DHEAD  64
#define MROWS  (BATCH * SLQ)   // 8192

// ---------------------------------------------------------------------------
// Scratch (device globals; no allocation allowed)
// ---------------------------------------------------------------------------
__device__ float g_q  [(size_t)MROWS * DMODEL];
__device__ float g_k  [(size_t)BATCH * SLK * DMODEL];
__device__ float g_v  [(size_t)BATCH * SLK * DMODEL];
__device__ float g_att[(size_t)MROWS * DMODEL];
__device__ float g_ao [(size_t)MROWS * DMODEL];
__device__ float g_f1 [(size_t)MROWS * DMODEL];
__device__ float g_y  [(size_t)MROWS * DMODEL];
__device__ int   g_valid[BATCH];

// ---------------------------------------------------------------------------
// valid_lens[b] = count of nonzero mask entries in row b
// ---------------------------------------------------------------------------
__global__ void valid_kernel(const int* __restrict__ mask) {
    __shared__ int red[256];
    int b = blockIdx.x;
    int cnt = 0;
    for (int i = threadIdx.x; i < SLK; i += 256)
        cnt += (mask[b * SLK + i] != 0) ? 1 : 0;
    red[threadIdx.x] = cnt;
    __syncthreads();
    for (int s = 128; s > 0; s >>= 1) {
        if (threadIdx.x < s) red[threadIdx.x] += red[threadIdx.x + s];
        __syncthreads();
    }
    if (threadIdx.x == 0) g_valid[b] = red[0];
}

// ---------------------------------------------------------------------------
// TF32 mma helpers
// ---------------------------------------------------------------------------
__device__ __forceinline__ unsigned f2tf(float f) {
    unsigned u;
    asm("cvt.rna.tf32.f32 %0, %1;" : "=r"(u) : "f"(f));
    return u;
}

__device__ __forceinline__ void mma_tf32(float c[4],
                                         const unsigned a[4],
                                         const unsigned b[2]) {
    asm volatile(
        "mma.sync.aligned.m16n8k8.row.col.f32.tf32.tf32.f32 "
        "{%0,%1,%2,%3}, {%4,%5,%6,%7}, {%8,%9}, {%0,%1,%2,%3};"
        : "+f"(c[0]), "+f"(c[1]), "+f"(c[2]), "+f"(c[3])
        : "r"(a[0]), "r"(a[1]), "r"(a[2]), "r"(a[3]),
          "r"(b[0]), "r"(b[1]));
}

// ---------------------------------------------------------------------------
// TF32 tensor-core GEMM core (128x128 tile, BK=16 double-buffered, 8 warps).
// A smem: per-row k-interleaved pairs (k, k+4), stride 24 -> a-frag LDS.64.
// B smem: [kchunk][t][n][pair], t-row stride 264 -> b-frag LDS.64.
// Shared buffers passed as 2D array references so ptxas keeps the buffer
// flip as pointer select (the R12 flat-index version regressed 99->141us).
// MODE: 0=plain, 1=+bias,ReLU, 2=+bias,+residual(g_ao)
// ---------------------------------------------------------------------------
#define GK DMODEL
#define GN DMODEL
#define ASTR 24
#define BTR  264
#define BCH  (4 * BTR)   // 1056

template<int MODE>
__device__ __forceinline__ void gemm_body(const float* __restrict__ A,
                                          const float* __restrict__ Bm,
                                          float* __restrict__ C,
                                          const float* __restrict__ bias,
                                          unsigned (&As)[2][128 * ASTR],
                                          unsigned (&Bs)[2][2 * BCH],
                                          int bx, int by)
{
    const int tid = threadIdx.x;
    const int warp = tid >> 5;
    const int lane = tid & 31;
    const int wm = warp >> 1;
    const int wn = warp & 1;
    const int g  = lane >> 2;
    const int t  = lane & 3;

    float acc[2][8][4];
#pragma unroll
    for (int mi = 0; mi < 2; mi++)
#pragma unroll
        for (int nj = 0; nj < 8; nj++)
#pragma unroll
            for (int q = 0; q < 4; q++) acc[mi][nj][q] = 0.0f;

    const int arow = tid >> 1;
    const int akc  = (tid & 1) * 8;
    const int bn4  = (tid & 31) * 4;
    const int bkrw = tid >> 5;
    const int bkkc = bkrw >> 2;
    const int btb  = bkrw & 3;

    const float* Ag  = A  + (size_t)(by * 128 + arow) * GK + akc;
    const float* BgL = Bm + (size_t)(bkkc * 8 + btb) * GN + bx * 128 + bn4;

    float4 pa0, pa1, pb0, pb1;

    pa0 = *(const float4*)(Ag);
    pa1 = *(const float4*)(Ag + 4);
    pb0 = *(const float4*)(BgL);
    pb1 = *(const float4*)(BgL + 4 * GN);
    {
        unsigned* as = &As[0][arow * ASTR + akc];
        *(uint4*)as       = make_uint4(f2tf(pa0.x), f2tf(pa1.x), f2tf(pa0.y), f2tf(pa1.y));
        *(uint4*)(as + 4) = make_uint4(f2tf(pa0.z), f2tf(pa1.z), f2tf(pa0.w), f2tf(pa1.w));
        unsigned* bs = &Bs[0][bkkc * BCH + btb * BTR + bn4 * 2];
        *(uint4*)bs       = make_uint4(f2tf(pb0.x), f2tf(pb1.x), f2tf(pb0.y), f2tf(pb1.y));
        *(uint4*)(bs + 4) = make_uint4(f2tf(pb0.z), f2tf(pb1.z), f2tf(pb0.w), f2tf(pb1.w));
    }
    __syncthreads();

    const int NKT = GK / 16;   // 48
    int cur = 0;
#pragma unroll 1
    for (int kt = 0; kt < NKT; kt++) {
        if (kt + 1 < NKT) {
            const float* ag = Ag + (kt + 1) * 16;
            const float* bl = BgL + (size_t)(kt + 1) * 16 * GN;
            pa0 = *(const float4*)(ag);
            pa1 = *(const float4*)(ag + 4);
            pb0 = *(const float4*)(bl);
            pb1 = *(const float4*)(bl + 4 * GN);
        }

#pragma unroll
        for (int kk = 0; kk < 16; kk += 8) {
            const int kkc = kk >> 3;
            unsigned af[2][4], bf[8][2];
#pragma unroll
            for (int mi = 0; mi < 2; mi++) {
                const int r = wm * 32 + mi * 16 + g;
                uint2 q0 = *(const uint2*)&As[cur][r * ASTR + kk + 2 * t];
                uint2 q1 = *(const uint2*)&As[cur][(r + 8) * ASTR + kk + 2 * t];
                af[mi][0] = q0.x; af[mi][1] = q1.x;
                af[mi][2] = q0.y; af[mi][3] = q1.y;
            }
#pragma unroll
            for (int nj = 0; nj < 8; nj++) {
                const int c = wn * 64 + nj * 8 + g;
                uint2 qb = *(const uint2*)&Bs[cur][kkc * BCH + t * BTR + c * 2];
                bf[nj][0] = qb.x; bf[nj][1] = qb.y;
            }
#pragma unroll
            for (int mi = 0; mi < 2; mi++)
#pragma unroll
                for (int nj = 0; nj < 8; nj++)
                    mma_tf32(acc[mi][nj], af[mi], bf[nj]);
        }

        if (kt + 1 < NKT) {
            const int nxt = cur ^ 1;
            unsigned* as = &As[nxt][arow * ASTR + akc];
            *(uint4*)as       = make_uint4(f2tf(pa0.x), f2tf(pa1.x), f2tf(pa0.y), f2tf(pa1.y));
            *(uint4*)(as + 4) = make_uint4(f2tf(pa0.z), f2tf(pa1.z), f2tf(pa0.w), f2tf(pa1.w));
            unsigned* bs = &Bs[nxt][bkkc * BCH + btb * BTR + bn4 * 2];
            *(uint4*)bs       = make_uint4(f2tf(pb0.x), f2tf(pb1.x), f2tf(pb0.y), f2tf(pb1.y));
            *(uint4*)(bs + 4) = make_uint4(f2tf(pb0.z), f2tf(pb1.z), f2tf(pb0.w), f2tf(pb1.w));
            __syncthreads();
            cur = nxt;
        }
    }

    const int row0 = by * 128 + wm * 32;
    const int col0 = bx * 128 + wn * 64;
#pragma unroll
    for (int mi = 0; mi < 2; mi++) {
#pragma unroll
        for (int nj = 0; nj < 8; nj++) {
            const int r = row0 + mi * 16 + g;
            const int c = col0 + nj * 8 + t * 2;
            float v0 = acc[mi][nj][0], v1 = acc[mi][nj][1];
            float v2 = acc[mi][nj][2], v3 = acc[mi][nj][3];
            if (MODE >= 1) {
                const float bb0 = bias[c], bb1 = bias[c + 1];
                v0 += bb0; v1 += bb1; v2 += bb0; v3 += bb1;
            }
            if (MODE == 1) {
                v0 = fmaxf(v0, 0.0f); v1 = fmaxf(v1, 0.0f);
                v2 = fmaxf(v2, 0.0f); v3 = fmaxf(v3, 0.0f);
            }
            if (MODE == 2) {
                const float* rr0 = g_ao + (size_t)r * GN + c;
                const float* rr1 = g_ao + (size_t)(r + 8) * GN + c;
                v0 += rr0[0]; v1 += rr0[1];
                v2 += rr1[0]; v3 += rr1[1];
            }
            *(float2*)(C + (size_t)r * GN + c)       = make_float2(v0, v1);
            *(float2*)(C + (size_t)(r + 8) * GN + c) = make_float2(v2, v3);
        }
    }
}

// Fused QKV projection: blockIdx.z selects {queries@Wq->g_q, keys@Wk->g_k,
// values@Wv->g_v}. 1152 CTAs -> tail wave amortized across all three GEMMs.
__global__ __launch_bounds__(256, 2)
void qkv_kernel(const float* __restrict__ qin, const float* __restrict__ kin,
                const float* __restrict__ vin, const float* __restrict__ Wq,
                const float* __restrict__ Wk, const float* __restrict__ Wv)
{
    __shared__ unsigned As[2][128 * ASTR];
    __shared__ unsigned Bs[2][2 * BCH];
    const int z = blockIdx.z;
    const float* A  = (z == 0) ? qin : (z == 1) ? kin : vin;
    const float* Bm = (z == 0) ? Wq  : (z == 1) ? Wk  : Wv;
    float* C        = (z == 0) ? g_q : (z == 1) ? g_k : g_v;
    gemm_body<0>(A, Bm, C, nullptr, As, Bs, blockIdx.x, blockIdx.y);
}

// Serial GEMM chain after attention
template<int ASEL, int CSEL, int MODE>
__global__ __launch_bounds__(256, 2)
void tgemm_kernel(const float* __restrict__ Bm, const float* __restrict__ bias)
{
    __shared__ unsigned As[2][128 * ASTR];
    __shared__ unsigned Bs[2][2 * BCH];
    const float* A = (ASEL == 1) ? g_att : (ASEL == 2) ? g_ao : g_f1;
    float* C = (CSEL == 3) ? g_ao : (CSEL == 4) ? g_f1 : g_y;
    gemm_body<MODE>(A, Bm, C, bias, As, Bs, blockIdx.x, blockIdx.y);
}

// ---------------------------------------------------------------------------
// Tensor-core flash attention (tf32 mma), single-buffered (R9 structure).
// __launch_bounds__(256, 2): cap regs at 128 so two CTAs co-reside per SM
// (2 x (105+1) KB smem fits the 228 KB/SM budget) — overlaps the serial
// load->QK->softmax->PV chains of two independent CTAs.
// ---------------------------------------------------------------------------
#define BQ   128
#define BKT  64
#define QSTR 72
#define KSTR 72
#define VTR  136
#define VCH  (4 * VTR)    // 544
#define PSTR 68
#define ATTN_SMEM ((BQ*QSTR + BKT*KSTR + 8*VCH + BQ*PSTR) * 4)  // 107520 B

__global__ __launch_bounds__(256, 2)
void attn_kernel() {
    extern __shared__ unsigned smu[];
    unsigned* Qs = smu;                    // [q][d-interleaved] stride 72
    unsigned* Ks = Qs + BQ * QSTR;         // [c][d-interleaved] stride 72
    unsigned* Vs = Ks + BKT * KSTR;        // [kvc][t][d][pair]
    unsigned* Ps = Vs + 8 * VCH;           // per-warp [16][64] stride 68

    const int qt = blockIdx.x;
    const int h  = blockIdx.y;
    const int b  = blockIdx.z;
    const int tid  = threadIdx.x;
    const int warp = tid >> 5;
    const int lane = tid & 31;
    const int g = lane >> 2;
    const int t = lane & 3;
    const int R0 = warp * 16;
    unsigned* Pw = Ps + R0 * PSTR;

    const int valid = g_valid[b];
    const int nkt = (valid > 0) ? ((valid + BKT - 1) / BKT) : (SLK / BKT);

    const float* Qb = g_q + ((size_t)b * SLQ + qt * BQ) * DMODEL + h * DHEAD;
    const float* Kb = g_k + (size_t)b * SLK * DMODEL + h * DHEAD;
    const float* Vb = g_v + (size_t)b * SLK * DMODEL + h * DHEAD;

    // load Q tile: k-interleaved pairs, scaled by 1/8, tf32
#pragma unroll
    for (int it = 0; it < 4; it++) {
        int idx = it * 256 + tid;
        int r = idx >> 3, c8 = idx & 7;
        const float* p = Qb + (size_t)r * DMODEL + c8 * 8;
        float4 lo = *(const float4*)(p);
        float4 hi = *(const float4*)(p + 4);
        unsigned* q = &Qs[r * QSTR + c8 * 8];
        *(uint4*)q       = make_uint4(f2tf(lo.x * 0.125f), f2tf(hi.x * 0.125f),
                                      f2tf(lo.y * 0.125f), f2tf(hi.y * 0.125f));
        *(uint4*)(q + 4) = make_uint4(f2tf(lo.z * 0.125f), f2tf(hi.z * 0.125f),
                                      f2tf(lo.w * 0.125f), f2tf(hi.w * 0.125f));
    }

    float m_lo = -1e30f, m_hi = -1e30f, l_lo = 0.0f, l_hi = 0.0f;
    float oa[8][4];
#pragma unroll
    for (int nb = 0; nb < 8; nb++)
#pragma unroll
        for (int q = 0; q < 4; q++) oa[nb][q] = 0.0f;

    // V loader mapping
    const int vd8 = (tid & 7) * 8;
    const int vrp = tid >> 3;
    const int vkvc = vrp >> 2;
    const int vtt  = vrp & 3;

#pragma unroll 1
    for (int kt = 0; kt < nkt; kt++) {
        __syncthreads();   // prev-tile K/V reads complete (also covers Q init)

        // K tile: k-interleaved rows
#pragma unroll
        for (int it = 0; it < 2; it++) {
            int idx = it * 256 + tid;
            int r = idx >> 3, c8 = idx & 7;
            const float* p = Kb + (size_t)(kt * BKT + r) * DMODEL + c8 * 8;
            float4 lo = *(const float4*)(p);
            float4 hi = *(const float4*)(p + 4);
            unsigned* q = &Ks[r * KSTR + c8 * 8];
            *(uint4*)q       = make_uint4(f2tf(lo.x), f2tf(hi.x), f2tf(lo.y), f2tf(hi.y));
            *(uint4*)(q + 4) = make_uint4(f2tf(lo.z), f2tf(hi.z), f2tf(lo.w), f2tf(hi.w));
        }
        // V tile: [kvc][t][d][pair]; thread reads rows kv0, kv0+4
        {
            const float* p0 = Vb + (size_t)(kt * BKT + vkvc * 8 + vtt) * DMODEL + vd8;
            const float* p1 = p0 + 4 * DMODEL;
            float4 lo0 = *(const float4*)(p0);
            float4 lo1 = *(const float4*)(p0 + 4);
            float4 hi0 = *(const float4*)(p1);
            float4 hi1 = *(const float4*)(p1 + 4);
            unsigned* vdst = &Vs[vkvc * VCH + vtt * VTR + vd8 * 2];
            *(uint4*)(vdst)      = make_uint4(f2tf(lo0.x), f2tf(hi0.x), f2tf(lo0.y), f2tf(hi0.y));
            *(uint4*)(vdst + 4)  = make_uint4(f2tf(lo0.z), f2tf(hi0.z), f2tf(lo0.w), f2tf(hi0.w));
            *(uint4*)(vdst + 8)  = make_uint4(f2tf(lo1.x), f2tf(hi1.x), f2tf(lo1.y), f2tf(hi1.y));
            *(uint4*)(vdst + 12) = make_uint4(f2tf(lo1.z), f2tf(hi1.z), f2tf(lo1.w), f2tf(hi1.w));
        }
        __syncthreads();

        // S = Q K^T  (64 mmas per warp)
        float sa[8][4];
#pragma unroll
        for (int nb = 0; nb < 8; nb++)
#pragma unroll
            for (int q = 0; q < 4; q++) sa[nb][q] = 0.0f;

#pragma unroll
        for (int kb = 0; kb < 8; kb++) {
            unsigned af[4];
            uint2 q0 = *(const uint2*)&Qs[(R0 + g) * QSTR + kb * 8 + 2 * t];
            uint2 q1 = *(const uint2*)&Qs[(R0 + g + 8) * QSTR + kb * 8 + 2 * t];
            af[0] = q0.x; af[1] = q1.x; af[2] = q0.y; af[3] = q1.y;
#pragma unroll
            for (int nb = 0; nb < 8; nb++) {
                unsigned bf[2];
                uint2 qk = *(const uint2*)&Ks[(nb * 8 + g) * KSTR + kb * 8 + 2 * t];
                bf[0] = qk.x; bf[1] = qk.y;
                mma_tf32(sa[nb], af, bf);
            }
        }

        // mask columns >= valid
        const int cbase = kt * BKT + 2 * t;
#pragma unroll
        for (int nb = 0; nb < 8; nb++) {
            const int c0 = cbase + nb * 8;
            if (c0     >= valid) { sa[nb][0] = -1e6f; sa[nb][2] = -1e6f; }
            if (c0 + 1 >= valid) { sa[nb][1] = -1e6f; sa[nb][3] = -1e6f; }
        }

        // online softmax (rows g and g+8 of this warp's 16)
        float tm_lo = -1e30f, tm_hi = -1e30f;
#pragma unroll
        for (int nb = 0; nb < 8; nb++) {
            tm_lo = fmaxf(tm_lo, fmaxf(sa[nb][0], sa[nb][1]));
            tm_hi = fmaxf(tm_hi, fmaxf(sa[nb][2], sa[nb][3]));
        }
#pragma unroll
        for (int off = 1; off < 4; off <<= 1) {
            tm_lo = fmaxf(tm_lo, __shfl_xor_sync(0xffffffffu, tm_lo, off));
            tm_hi = fmaxf(tm_hi, __shfl_xor_sync(0xffffffffu, tm_hi, off));
        }
        const float mn_lo = fmaxf(m_lo, tm_lo);
        const float mn_hi = fmaxf(m_hi, tm_hi);
        const float corr_lo = __expf(m_lo - mn_lo);
        const float corr_hi = __expf(m_hi - mn_hi);
        m_lo = mn_lo; m_hi = mn_hi;

        float ts_lo = 0.0f, ts_hi = 0.0f;
#pragma unroll
        for (int nb = 0; nb < 8; nb++) {
            float p0 = __expf(sa[nb][0] - mn_lo);
            float p1 = __expf(sa[nb][1] - mn_lo);
            float p2 = __expf(sa[nb][2] - mn_hi);
            float p3 = __expf(sa[nb][3] - mn_hi);
            ts_lo += p0 + p1;
            ts_hi += p2 + p3;
            *(uint2*)&Pw[g * PSTR + nb * 8 + 2 * t] =
                make_uint2(f2tf(p0), f2tf(p1));
            *(uint2*)&Pw[(g + 8) * PSTR + nb * 8 + 2 * t] =
                make_uint2(f2tf(p2), f2tf(p3));
        }
#pragma unroll
        for (int off = 1; off < 4; off <<= 1) {
            ts_lo += __shfl_xor_sync(0xffffffffu, ts_lo, off);
            ts_hi += __shfl_xor_sync(0xffffffffu, ts_hi, off);
        }
        l_lo = l_lo * corr_lo + ts_lo;
        l_hi = l_hi * corr_hi + ts_hi;
#pragma unroll
        for (int nb = 0; nb < 8; nb++) {
            oa[nb][0] *= corr_lo; oa[nb][1] *= corr_lo;
            oa[nb][2] *= corr_hi; oa[nb][3] *= corr_hi;
        }
        __syncwarp();

        // O += P V  (64 mmas per warp)
#pragma unroll
        for (int kb = 0; kb < 8; kb++) {
            unsigned af[4];
            const unsigned* pp = &Pw[g * PSTR + kb * 8 + t];
            af[0] = pp[0];
            af[1] = pp[8 * PSTR];
            af[2] = pp[4];
            af[3] = pp[8 * PSTR + 4];
#pragma unroll
            for (int nb = 0; nb < 8; nb++) {
                unsigned bf[2];
                uint2 qv = *(const uint2*)&Vs[kb * VCH + t * VTR + (nb * 8 + g) * 2];
                bf[0] = qv.x; bf[1] = qv.y;
                mma_tf32(oa[nb], af, bf);
            }
        }
        __syncwarp();   // Pw reads done before next tile's softmax overwrites
    }

    // epilogue
    const float inv_lo = 1.0f / l_lo;
    const float inv_hi = 1.0f / l_hi;
    const int row_lo = qt * BQ + R0 + g;
    float* Ob = g_att + ((size_t)b * SLQ) * DMODEL + h * DHEAD;
#pragma unroll
    for (int nb = 0; nb < 8; nb++) {
        const int c = nb * 8 + 2 * t;
        *(float2*)(Ob + (size_t)row_lo * DMODEL + c) =
            make_float2(oa[nb][0] * inv_lo, oa[nb][1] * inv_lo);
        *(float2*)(Ob + (size_t)(row_lo + 8) * DMODEL + c) =
            make_float2(oa[nb][2] * inv_hi, oa[nb][3] * inv_hi);
    }
}

// ---------------------------------------------------------------------------
// LayerNorm over g_y rows -> out (warp-shfl reductions, 2 barriers)
// ---------------------------------------------------------------------------
__global__ __launch_bounds__(256)
void ln_kernel(const float* __restrict__ gamma,
               const float* __restrict__ beta,
               float* __restrict__ out)
{
    __shared__ float ws[8], ws2[8];
    const int row = blockIdx.x;
    const int tid = threadIdx.x;
    const float* y = g_y + (size_t)row * DMODEL;
    float v[3], s = 0.0f, s2 = 0.0f;
#pragma unroll
    for (int t = 0; t < 3; t++) {
        v[t] = y[tid + t * 256];
        s += v[t]; s2 += v[t] * v[t];
    }
#pragma unroll
    for (int off = 16; off > 0; off >>= 1) {
        s  += __shfl_xor_sync(0xffffffffu, s,  off);
        s2 += __shfl_xor_sync(0xffffffffu, s2, off);
    }
    if ((tid & 31) == 0) { ws[tid >> 5] = s; ws2[tid >> 5] = s2; }
    __syncthreads();
    float tot = 0.0f, tot2 = 0.0f;
#pragma unroll
    for (int i = 0; i < 8; i++) { tot += ws[i]; tot2 += ws2[i]; }
    const float mean = tot * (1.0f / DMODEL);
    const float var  = tot2 * (1.0f / DMODEL) - mean * mean;
    const float inv  = rsqrtf(var + 1e-5f);
#pragma unroll
    for (int t = 0; t < 3; t++) {
        int col = tid + t * 256;
        out[(size_t)row * DMODEL + col] = (v[t] - mean) * inv * gamma[col] + beta[col];
    }
}

// ---------------------------------------------------------------------------
// Launch
// ---------------------------------------------------------------------------
extern "C" void kernel_launch(void* const* d_in, const int* in_sizes, int n_in,
                              void* d_out, int out_size)
{
    (void)in_sizes; (void)n_in; (void)out_size;
    const float* queries = (const float*)d_in[0];
    const float* keys    = (const float*)d_in[1];
    const float* values  = (const float*)d_in[2];
    const int*   mask    = (const int*)  d_in[3];
    const float* Wq = (const float*)d_in[4];
    const float* Wk = (const float*)d_in[5];
    const float* Wv = (const float*)d_in[6];
    const float* Wo = (const float*)d_in[7];
    const float* W1 = (const float*)d_in[8];
    const float* b1 = (const float*)d_in[9];
    const float* W2 = (const float*)d_in[10];
    const float* b2 = (const float*)d_in[11];
    const float* lg = (const float*)d_in[12];
    const float* lb = (const float*)d_in[13];
    float* out = (float*)d_out;

    valid_kernel<<<BATCH, 256>>>(mask);

    qkv_kernel<<<dim3(GN / 128, MROWS / 128, 3), 256>>>(
        queries, keys, values, Wq, Wk, Wv);

    cudaFuncSetAttribute(attn_kernel,
                         cudaFuncAttributeMaxDynamicSharedMemorySize,
                         (int)ATTN_SMEM);
    attn_kernel<<<dim3(SLQ / BQ, NHEAD, BATCH), 256, ATTN_SMEM>>>();

    dim3 ggrid(GN / 128, MROWS / 128);   // (6, 64)
    tgemm_kernel<1, 3, 0><<<ggrid, 256>>>(Wo, nullptr);  // att_out
    tgemm_kernel<2, 4, 1><<<ggrid, 256>>>(W1, b1);       // relu(ffn1)
    tgemm_kernel<3, 5, 2><<<ggrid, 256>>>(W2, b2);       // y = ffn2 + att_out

    ln_kernel<<<MROWS, 256>>>(lg, lb, out);
}